// round 10
// baseline (speedup 1.0000x reference)
#include <cuda_runtime.h>

// ForgetMult: h_t = f_t*x_t + (1-f_t)*h_{t-1}
// f,x: (4096, 16, 512) fp32. out inclusive, h_0 = hidden_init.
//
// Single-pass chunked scan, float4 channels, no staging (phase 4 re-reads
// f,x from L2). vs R8:
//   - SINGLE kernel: no reset launch. Flags are monotonic per-launch
//     version counters (each flag incremented exactly once per launch by
//     its unique owner; waiters derive the target version from their own
//     flag's pre-launch value).
//   - PERSISTENT grid: 296 blocks (2/SM x 148), each loops over chunks
//     bid, bid+296, ... Deadlock-free: chunk deps have strictly lower
//     chunk index; all blocks are co-resident.

#define SEQ_LEN  4096
#define C4       2048                  // float4 channels
#define SL       16                    // timesteps per thread
#define SUBS     16                    // sub-chunks (warps) per block
#define TILE_C4  32                    // f4 channels per block
#define TB       (SL * SUBS)           // 256 timesteps per chunk
#define TBLKS    (SEQ_LEN / TB)        // 16
#define TILES    (C4 / TILE_C4)        // 64
#define NCHUNKS  (TILES * TBLKS)       // 1024
#define NTHREADS (TILE_C4 * SUBS)      // 512
#define GRIDSZ   296                   // 2 blocks/SM x 148 SMs

__device__ float4 g_aggA[TBLKS * C4];
__device__ float4 g_aggB[TBLKS * C4];
__device__ float4 g_prefH[C4];           // h at end of time-block 0
__device__ int    g_flag[NCHUNKS];       // monotonic version counters (0-init)

__device__ __forceinline__ float4 f4_fma(float4 a, float4 h, float4 b) {
    return make_float4(fmaf(a.x, h.x, b.x), fmaf(a.y, h.y, b.y),
                       fmaf(a.z, h.z, b.z), fmaf(a.w, h.w, b.w));
}
__device__ __forceinline__ float4 f4_mul(float4 a, float4 b) {
    return make_float4(a.x * b.x, a.y * b.y, a.z * b.z, a.w * b.w);
}
__device__ __forceinline__ int ld_acquire_gpu(const int* p) {
    int v;
    asm volatile("ld.acquire.gpu.global.b32 %0, [%1];" : "=r"(v) : "l"(p) : "memory");
    return v;
}
__device__ __forceinline__ void st_release_gpu(int* p, int v) {
    asm volatile("st.release.gpu.global.b32 [%0], %1;" :: "l"(p), "r"(v) : "memory");
}

__global__ __launch_bounds__(NTHREADS, 2)
void forget_mult_v9_kernel(
    const float4* __restrict__ f,
    const float4* __restrict__ x,
    const float4* __restrict__ h0,
    float4* __restrict__ out)
{
    __shared__ float4 sA[SUBS * TILE_C4];
    __shared__ float4 sB[SUBS * TILE_C4];
    __shared__ float4 sHin[TILE_C4];
    __shared__ int    sVer;              // this launch's target flag version

    const int tid = threadIdx.x;
    const int c   = tid & (TILE_C4 - 1);
    const int s   = tid >> 5;            // warp id = sub-chunk

    for (int chunk = blockIdx.x; chunk < NCHUNKS; chunk += GRIDSZ) {
        const int tile = chunk >> 4;               // / TBLKS
        const int tblk = chunk & (TBLKS - 1);      // fastest-varying

        // Baseline: our own flag is written only by us, later -> its current
        // value is this launch's N-1. Target version for predecessors = N.
        if (tid == 0) sVer = g_flag[chunk] + 1;

        const int cg = tile * TILE_C4 + c;
        const int t0 = tblk * TB + s * SL;

        const float4* fp = f + (size_t)t0 * C4 + cg;
        const float4* xp = x + (size_t)t0 * C4 + cg;

        // ---- Phase 1: stream loads (L2-resident), fold composite ----
        float4 cA = make_float4(1.f, 1.f, 1.f, 1.f);
        float4 cB = make_float4(0.f, 0.f, 0.f, 0.f);
#pragma unroll
        for (int i = 0; i < SL; i++) {
            float4 ft = fp[(size_t)i * C4];
            float4 xt = xp[(size_t)i * C4];
            float4 a = make_float4(1.f - ft.x, 1.f - ft.y, 1.f - ft.z, 1.f - ft.w);
            float4 b = f4_mul(ft, xt);
            cB = f4_fma(a, cB, b);
            cA = f4_mul(cA, a);
        }

        // ---- Phase 2: Hillis-Steele over 16 sub-chunks ----
        sA[s * TILE_C4 + c] = cA;
        sB[s * TILE_C4 + c] = cB;
        __syncthreads();                 // also publishes sVer
        const int ver = sVer;
#pragma unroll
        for (int d = 1; d < SUBS; d <<= 1) {
            float4 pA, pB;
            if (s >= d) {
                pA = sA[(s - d) * TILE_C4 + c];
                pB = sB[(s - d) * TILE_C4 + c];
            }
            __syncthreads();
            if (s >= d) {
                cB = f4_fma(cA, pB, cB);     // cur ∘ prev
                cA = f4_mul(cA, pA);
                sA[s * TILE_C4 + c] = cA;
                sB[s * TILE_C4 + c] = cB;
            }
            __syncthreads();
        }
        float4 exA = make_float4(1.f, 1.f, 1.f, 1.f);
        float4 exB = make_float4(0.f, 0.f, 0.f, 0.f);
        if (s > 0) {
            exA = sA[(s - 1) * TILE_C4 + c];
            exB = sB[(s - 1) * TILE_C4 + c];
        }

        // ---- Phase 3: parallel look-back (warp 0 only) ----
        if (tid < TILE_C4) {
            const float4 blkA = sA[(SUBS - 1) * TILE_C4 + tid];
            const float4 blkB = sB[(SUBS - 1) * TILE_C4 + tid];
            const int cg0 = tile * TILE_C4 + tid;
            float4 hin_blk;
            if (tblk == 0) {
                hin_blk = h0[cg0];
                g_prefH[cg0] = f4_fma(blkA, hin_blk, blkB);
                __syncwarp(0xFFFFFFFFu);
                if (tid == 0) st_release_gpu(&g_flag[chunk], ver);
            } else {
                g_aggA[(size_t)tblk * C4 + cg0] = blkA;
                g_aggB[(size_t)tblk * C4 + cg0] = blkB;
                __syncwarp(0xFFFFFFFFu);
                if (tid == 0) st_release_gpu(&g_flag[chunk], ver);

                // Wait once for all predecessors to reach this version.
                const int base = tile * TBLKS;
                for (int j = tblk - 1; j >= 0; j--)
                    while (ld_acquire_gpu(&g_flag[base + j]) < ver) { }

                // Fold independent aggregate loads (overlapped by HW).
                float4 accA = make_float4(1.f, 1.f, 1.f, 1.f);
                float4 accB = make_float4(0.f, 0.f, 0.f, 0.f);
#pragma unroll 5
                for (int j = tblk - 1; j >= 1; j--) {
                    float4 aj = g_aggA[(size_t)j * C4 + cg0];
                    float4 bj = g_aggB[(size_t)j * C4 + cg0];
                    accB = f4_fma(accA, bj, accB);
                    accA = f4_mul(accA, aj);
                }
                float4 hpre = g_prefH[cg0];
                hin_blk = f4_fma(accA, hpre, accB);
            }
            sHin[tid] = hin_blk;
        }
        __syncthreads();

        // ---- Phase 4: re-read f,x (L2-hot), rebuild a,b, replay, store ----
        float4 h = f4_fma(exA, sHin[c], exB);
        float4* op = out + (size_t)t0 * C4 + cg;
#pragma unroll
        for (int i = 0; i < SL; i++) {
            float4 ft = __ldcs(fp + (size_t)i * C4);   // 2nd use: evict-first
            float4 xt = __ldcs(xp + (size_t)i * C4);
            float4 a = make_float4(1.f - ft.x, 1.f - ft.y, 1.f - ft.z, 1.f - ft.w);
            float4 b = f4_mul(ft, xt);
            h = f4_fma(a, h, b);
            __stcs(op + (size_t)i * C4, h);
        }
        __syncthreads();   // protect sA/sB/sHin before next chunk iteration
    }
}

extern "C" void kernel_launch(void* const* d_in, const int* in_sizes, int n_in,
                              void* d_out, int out_size)
{
    const float4* f  = (const float4*)d_in[0];
    const float4* x  = (const float4*)d_in[1];
    const float4* h0 = (const float4*)d_in[2];
    float4* out = (float4*)d_out;

    dim3 grid(GRIDSZ);       // persistent: 2 blocks/SM x 148 SMs, all resident
    dim3 block(NTHREADS);
    forget_mult_v9_kernel<<<grid, block>>>(f, x, h0, out);
}

// round 11
// speedup vs baseline: 1.1528x; 1.1528x over previous
#include <cuda_runtime.h>

// ForgetMult: h_t = f_t*x_t + (1-f_t)*h_{t-1}
// f,x: (4096, 16, 512) fp32. out inclusive, h_0 = hidden_init.
//
// Single-pass chunked scan, float4 channels, no staging (phase 4 re-reads
// f,x from L2). vs R8 (96.7us):
//   - TILE_C4 16 (was 32): 256-thread blocks, 64KB slab/block, 4 blocks/SM.
//     Same warps/SM and same 38MB in-flight slab set (L2-resident), but 4
//     independently-staggered block pipelines per SM so the load/store
//     phases of one block overlap the barrier/look-back phases of others.
//   - TB=256 kept -> look-back depth <= 15 (unchanged).

#define SEQ_LEN  4096
#define C4       2048                  // float4 channels
#define SL       16                    // timesteps per thread
#define SUBS     16                    // sub-chunks per block
#define TILE_C4  16                    // f4 channels per block (64 fp32)
#define TB       (SL * SUBS)           // 256 timesteps per block
#define TBLKS    (SEQ_LEN / TB)        // 16
#define TILES    (C4 / TILE_C4)        // 128
#define NTHREADS (TILE_C4 * SUBS)      // 256

__device__ float4 g_aggA[TBLKS * C4];
__device__ float4 g_aggB[TBLKS * C4];
__device__ float4 g_prefH[C4];            // h at end of time-block 0
__device__ int    g_flag[TBLKS * TILES];  // 0=none 1=agg ready 2=prefix ready

__device__ __forceinline__ float4 f4_fma(float4 a, float4 h, float4 b) {
    return make_float4(fmaf(a.x, h.x, b.x), fmaf(a.y, h.y, b.y),
                       fmaf(a.z, h.z, b.z), fmaf(a.w, h.w, b.w));
}
__device__ __forceinline__ float4 f4_mul(float4 a, float4 b) {
    return make_float4(a.x * b.x, a.y * b.y, a.z * b.z, a.w * b.w);
}
__device__ __forceinline__ int ld_acquire_gpu(const int* p) {
    int v;
    asm volatile("ld.acquire.gpu.global.b32 %0, [%1];" : "=r"(v) : "l"(p) : "memory");
    return v;
}
__device__ __forceinline__ void st_release_gpu(int* p, int v) {
    asm volatile("st.release.gpu.global.b32 [%0], %1;" :: "l"(p), "r"(v) : "memory");
}

__global__ void reset_flags_kernel()
{
    int i = blockIdx.x * blockDim.x + threadIdx.x;
    if (i < TBLKS * TILES) g_flag[i] = 0;
}

__global__ __launch_bounds__(NTHREADS, 4)
void forget_mult_v10_kernel(
    const float4* __restrict__ f,
    const float4* __restrict__ x,
    const float4* __restrict__ h0,
    float4* __restrict__ out)
{
    __shared__ float4 sA[SUBS * TILE_C4];
    __shared__ float4 sB[SUBS * TILE_C4];
    __shared__ float4 sHin[TILE_C4];

    const int tid  = threadIdx.x;
    const int c    = tid & (TILE_C4 - 1);       // f4 channel within tile
    const int s    = tid >> 4;                  // sub-chunk (half-warp granular)
    const int tile = blockIdx.x >> 4;           // / TBLKS
    const int tblk = blockIdx.x & (TBLKS - 1);  // fastest-varying in bid

    const int cg = tile * TILE_C4 + c;
    const int t0 = tblk * TB + s * SL;

    const float4* fp = f + (size_t)t0 * C4 + cg;
    const float4* xp = x + (size_t)t0 * C4 + cg;

    // ---- Phase 1: stream loads (lines stay L2-resident), fold composite ----
    float4 cA = make_float4(1.f, 1.f, 1.f, 1.f);
    float4 cB = make_float4(0.f, 0.f, 0.f, 0.f);
#pragma unroll
    for (int i = 0; i < SL; i++) {
        float4 ft = fp[(size_t)i * C4];   // default caching -> L2 keeps it
        float4 xt = xp[(size_t)i * C4];
        float4 a = make_float4(1.f - ft.x, 1.f - ft.y, 1.f - ft.z, 1.f - ft.w);
        float4 b = f4_mul(ft, xt);
        cB = f4_fma(a, cB, b);
        cA = f4_mul(cA, a);
    }

    // ---- Phase 2: Hillis-Steele over the 16 sub-chunks (4 rounds) ----
    sA[s * TILE_C4 + c] = cA;
    sB[s * TILE_C4 + c] = cB;
    __syncthreads();
#pragma unroll
    for (int d = 1; d < SUBS; d <<= 1) {
        float4 pA, pB;
        if (s >= d) {
            pA = sA[(s - d) * TILE_C4 + c];
            pB = sB[(s - d) * TILE_C4 + c];
        }
        __syncthreads();
        if (s >= d) {
            cB = f4_fma(cA, pB, cB);   // cur ∘ prev
            cA = f4_mul(cA, pA);
            sA[s * TILE_C4 + c] = cA;
            sB[s * TILE_C4 + c] = cB;
        }
        __syncthreads();
    }
    float4 exA = make_float4(1.f, 1.f, 1.f, 1.f);
    float4 exB = make_float4(0.f, 0.f, 0.f, 0.f);
    if (s > 0) {
        exA = sA[(s - 1) * TILE_C4 + c];
        exB = sB[(s - 1) * TILE_C4 + c];
    }

    // ---- Phase 3: parallel look-back (first half-warp of warp 0) ----
    if (tid < TILE_C4) {
        const float4 blkA = sA[(SUBS - 1) * TILE_C4 + tid];
        const float4 blkB = sB[(SUBS - 1) * TILE_C4 + tid];
        const int cg0 = tile * TILE_C4 + tid;
        float4 hin_blk;
        if (tblk == 0) {
            hin_blk = h0[cg0];
            g_prefH[cg0] = f4_fma(blkA, hin_blk, blkB);
            __syncwarp(0x0000FFFFu);
            if (tid == 0)
                st_release_gpu(&g_flag[0 * TILES + tile], 2);
        } else {
            g_aggA[(size_t)tblk * C4 + cg0] = blkA;
            g_aggB[(size_t)tblk * C4 + cg0] = blkB;
            __syncwarp(0x0000FFFFu);
            if (tid == 0)
                st_release_gpu(&g_flag[tblk * TILES + tile], 1);

            // Wait once for all predecessors (aggs j>=1, prefix j=0).
            for (int j = tblk - 1; j >= 1; j--)
                while (ld_acquire_gpu(&g_flag[j * TILES + tile]) < 1) { }
            while (ld_acquire_gpu(&g_flag[0 * TILES + tile]) < 2) { }

            // Fold: aggregate loads independent across j -> overlapped.
            float4 accA = make_float4(1.f, 1.f, 1.f, 1.f);
            float4 accB = make_float4(0.f, 0.f, 0.f, 0.f);
#pragma unroll 5
            for (int j = tblk - 1; j >= 1; j--) {
                float4 aj = g_aggA[(size_t)j * C4 + cg0];
                float4 bj = g_aggB[(size_t)j * C4 + cg0];
                accB = f4_fma(accA, bj, accB);
                accA = f4_mul(accA, aj);
            }
            float4 hpre = g_prefH[cg0];
            hin_blk = f4_fma(accA, hpre, accB);
        }
        sHin[tid] = hin_blk;
    }
    __syncthreads();

    // ---- Phase 4: re-read f,x (L2-hot), rebuild a,b, replay, store ----
    float4 h = f4_fma(exA, sHin[c], exB);
    float4* op = out + (size_t)t0 * C4 + cg;
#pragma unroll
    for (int i = 0; i < SL; i++) {
        float4 ft = __ldcs(fp + (size_t)i * C4);   // 2nd use: evict-first
        float4 xt = __ldcs(xp + (size_t)i * C4);
        float4 a = make_float4(1.f - ft.x, 1.f - ft.y, 1.f - ft.z, 1.f - ft.w);
        float4 b = f4_mul(ft, xt);
        h = f4_fma(a, h, b);
        __stcs(op + (size_t)i * C4, h);
    }
}

extern "C" void kernel_launch(void* const* d_in, const int* in_sizes, int n_in,
                              void* d_out, int out_size)
{
    const float4* f  = (const float4*)d_in[0];
    const float4* x  = (const float4*)d_in[1];
    const float4* h0 = (const float4*)d_in[2];
    float4* out = (float4*)d_out;

    reset_flags_kernel<<<(TBLKS * TILES + 255) / 256, 256>>>();

    dim3 grid(TILES * TBLKS);   // tblk fastest -> predecessors at lower bid
    dim3 block(NTHREADS);
    forget_mult_v10_kernel<<<grid, block>>>(f, x, h0, out);
}